// round 10
// baseline (speedup 1.0000x reference)
#include <cuda_runtime.h>
#include <cuda_bf16.h>

// Problem constants
#define BB     1024
#define SS     350
#define VOCAB  41
#define LAT    512
#define H1     256
#define H2     128
#define H3     32
#define G0DIM  768
#define G1DIM  384
#define G2DIM  96
#define INITD  416
#define BROWS  7
#define NCTA   147           // 147*7 = 1029 >= 1024
#define NT     768           // 24 warps, 6 per SMSP
#define PRED_OFF (BB*SS*VOCAB)
#define WSM    26            // Whh1 k4-slices kept in smem (of 32)

typedef unsigned long long ull;

// ------------------------- device scratch -----------------------------------
__device__ float  g_G0[VOCAB * G0DIM];
__device__ float  g_init[BB * INITD];
__device__ float4 g_Wt0 [64 * G0DIM];         // Whh0^T  [k4][f], K=256
__device__ float4 g_Wt1 [64 * G1DIM];         // Wih1^T  [k4][f], K=256
__device__ float4 g_Wt1h[32 * G1DIM];         // Whh1^T  [k4][f], K=128
__device__ float4 g_Wt2i[32 * G2DIM];         // Wih2^T  [k4][f], K=128
__device__ float4 g_Wt2h[ 8 * G2DIM];         // Whh2^T  [k4][f], K=32
__device__ float  g_WtInit[LAT * INITD];
__device__ float  g_WtIh0[LAT * G0DIM];

// ------------------------- helpers ------------------------------------------
__device__ __forceinline__ void ffma2(ull &d, ull a, ull b) {
    asm("fma.rn.f32x2 %0, %1, %2, %0;" : "+l"(d) : "l"(a), "l"(b));
}
__device__ __forceinline__ ull packf2(float lo, float hi) {
    ull v; asm("mov.b64 %0, {%1,%2};" : "=l"(v) : "f"(lo), "f"(hi)); return v;
}
__device__ __forceinline__ float hred(ull v) {
    float lo, hi;
    asm("mov.b64 {%0,%1}, %2;" : "=f"(lo), "=f"(hi) : "l"(v));
    return lo + hi;
}
__device__ __forceinline__ float sigf(float x) { return 1.0f / (1.0f + __expf(-x)); }

// ------------------------- prep kernels (exactly 5 launches) ----------------
// P1: Whh0^T + Wih1^T
__global__ void k_prepA(const float* __restrict__ Whh0, const float* __restrict__ Wih1) {
    int idx = blockIdx.x * blockDim.x + threadIdx.x;
    if (idx < G0DIM * 64) {                    // Whh0: 768x256
        int j = idx >> 6, k4 = idx & 63;
        const float* s = Whh0 + j * H1 + k4 * 4;
        g_Wt0[k4 * G0DIM + j] = make_float4(s[0], s[1], s[2], s[3]);
    }
    if (idx < G1DIM * 64) {                    // Wih1: 384x256
        int j = idx >> 6, k4 = idx & 63;
        const float* s = Wih1 + j * H1 + k4 * 4;
        g_Wt1[k4 * G1DIM + j] = make_float4(s[0], s[1], s[2], s[3]);
    }
}
// P2: Whh1^T + Wih2^T + Whh2^T
__global__ void k_prepB(const float* __restrict__ Whh1, const float* __restrict__ Wih2,
                        const float* __restrict__ Whh2) {
    int idx = blockIdx.x * blockDim.x + threadIdx.x;
    if (idx < G1DIM * 32) {                    // Whh1: 384x128
        int j = idx >> 5, k4 = idx & 31;
        const float* s = Whh1 + j * H2 + k4 * 4;
        g_Wt1h[k4 * G1DIM + j] = make_float4(s[0], s[1], s[2], s[3]);
    }
    if (idx < G2DIM * 32) {                    // Wih2: 96x128
        int f = idx >> 5, k4 = idx & 31;
        const float* s = Wih2 + f * H2 + k4 * 4;
        g_Wt2i[k4 * G2DIM + f] = make_float4(s[0], s[1], s[2], s[3]);
    }
    if (idx < G2DIM * 8) {                     // Whh2: 96x32
        int f = idx >> 3, k4 = idx & 7;
        const float* s = Whh2 + f * H3 + k4 * 4;
        g_Wt2h[k4 * G2DIM + f] = make_float4(s[0], s[1], s[2], s[3]);
    }
}
// P3: W_init^T + Wih0^T
__global__ void k_prepC(const float* __restrict__ W_init, const float* __restrict__ Wih0) {
    int idx = blockIdx.x * blockDim.x + threadIdx.x;
    if (idx < INITD * LAT) {
        int o = idx / LAT, k = idx % LAT;
        g_WtInit[k * INITD + o] = W_init[idx];
    }
    if (idx < G0DIM * LAT) {
        int j = idx / LAT, k = idx % LAT;
        g_WtIh0[k * G0DIM + j] = Wih0[idx];
    }
}
// P4: G0 table
__global__ void k_g0(const float* __restrict__ W_emb, const float* __restrict__ b_emb,
                     const float* __restrict__ bih0) {
    __shared__ float emb[LAT];
    int v = blockIdx.x;
    for (int k = threadIdx.x; k < LAT; k += blockDim.x)
        emb[k] = W_emb[k * VOCAB + v] + b_emb[k];
    __syncthreads();
    for (int j = threadIdx.x; j < G0DIM; j += blockDim.x) {
        float acc = bih0[j];
        for (int k = 0; k < LAT; k++)
            acc += emb[k] * g_WtIh0[k * G0DIM + j];
        g_G0[v * G0DIM + j] = acc;
    }
}
// P5: initial hidden states
__global__ void k_init(const float* __restrict__ latent, const float* __restrict__ b_init) {
    __shared__ float lat[8 * LAT];
    int b0 = blockIdx.x * 8;
    for (int i = threadIdx.x; i < 8 * LAT; i += 256) {
        int r = i >> 9, k = i & 511;
        lat[i] = latent[(b0 + r) * LAT + k];
    }
    __syncthreads();
    for (int o = threadIdx.x; o < INITD; o += 256) {
        float bi = b_init[o];
        float acc[8];
#pragma unroll
        for (int r = 0; r < 8; r++) acc[r] = bi;
        for (int k = 0; k < LAT; k++) {
            float w = g_WtInit[k * INITD + o];
#pragma unroll
            for (int r = 0; r < 8; r++) acc[r] += w * lat[(r << 9) + k];
        }
#pragma unroll
        for (int r = 0; r < 8; r++) g_init[(b0 + r) * INITD + o] = acc[r];
    }
}

// ------------------------- main persistent GRU kernel -----------------------
// smem layout (floats)
#define O_WHH1 0                               // 26*384*4 = 39936
#define O_GA   39936                           // 5376  (gh0 full / gi1 2x / gi2 4x)
#define O_GB   (O_GA + 5376)                   // 45312; 5376 (gh1 2 partials)
#define O_GC   (O_GB + 5376)                   // 50688; 1344 (gh2 2 partials)
#define O_GN   (O_GC + 1344)                   // 52032; 1792 (gin staging)
#define O_H0   (O_GN + 1792)                   // 53824; 1792
#define O_H1   (O_H0 + 1792)                   // 55616; 896
#define O_H2   (O_H1 + 896)                    // 56512; 224
#define O_TOK  (O_H2 + 224)                    // 56736
#define SMEM_FLOATS (O_TOK + 8)
#define SMEM_BYTES  (SMEM_FLOATS * 4)          // 226,976 bytes

__global__ void __launch_bounds__(NT, 1)
k_gru(const int* __restrict__ toks,
      const float* __restrict__ bhh0,
      const float* __restrict__ bih1, const float* __restrict__ bhh1,
      const float* __restrict__ bih2, const float* __restrict__ bhh2,
      const float* __restrict__ W_proj, const float* __restrict__ b_proj,
      float* __restrict__ out)
{
    extern __shared__ float sm[];
    float* sGA  = sm + O_GA;
    float* sGB  = sm + O_GB;
    float* sGC  = sm + O_GC;
    float* sGN  = sm + O_GN;
    float* h0   = sm + O_H0;
    float* h1   = sm + O_H1;
    float* h2   = sm + O_H2;
    int*   stok = (int*)(sm + O_TOK);

    const int tid  = threadIdx.x;
    const int lane = tid & 31;
    const int wrp  = tid >> 5;
    const int base = blockIdx.x * BROWS;

    // --- load Whh1^T slices 0..WSM-1 into smem ---
    {
        float4* d = (float4*)(sm + O_WHH1);
        const float4* s = g_Wt1h;
        for (int i = tid; i < WSM * G1DIM; i += NT) d[i] = s[i];
    }
    // --- initial hidden states (clamped rows) ---
    for (int i = tid; i < BROWS * H1; i += NT) {
        int r = i >> 8, k = i & 255;
        int b = base + r; if (b >= BB) b = BB - 1;
        h0[i] = g_init[b * INITD + k];
    }
    for (int i = tid; i < BROWS * H2; i += NT) {
        int r = i >> 7, k = i & 127;
        int b = base + r; if (b >= BB) b = BB - 1;
        h1[i] = g_init[b * INITD + H1 + k];
    }
    for (int i = tid; i < BROWS * H3; i += NT) {
        int r = i >> 5, k = i & 31;
        int b = base + r; if (b >= BB) b = BB - 1;
        h2[i] = g_init[b * INITD + H1 + H2 + k];
    }
    if (tid < BROWS) stok[tid] = 1;   // SOS

    // --- per-thread fixed preloads ---
    const float b0 = bhh0[tid];                                  // gh0 feat = tid
    const float b1i = (tid < G1DIM) ? bih1[tid] : 0.0f;          // gi1 lo-half
    const float b1h = (tid < G1DIM) ? bhh1[tid] : 0.0f;          // gh1 lo-half
    const float b2i = (tid < G2DIM) ? bih2[tid] : 0.0f;          // gi2 q==0
    const float b2h = (tid >= 384 && tid < 384 + G2DIM) ? bhh2[tid - 384] : 0.0f;
    float bp0 = 0.0f, bp1 = 0.0f;
    if (wrp < BROWS) { bp0 = b_proj[lane]; if (lane < 9) bp1 = b_proj[32 + lane]; }
    __syncthreads();

    for (int t = 0; t <= SS; t++) {
        // ===== fused: logits+argmax of step t-1 (warps 0..6) ================
        if (t > 0 && wrp < BROWS) {
            const int r = wrp, b = base + r, tprev = t - 1;
            const float4* hp = (const float4*)(h2 + r * H3);
            float4 hv[8];
#pragma unroll
            for (int q = 0; q < 8; q++) hv[q] = hp[q];
            float acc0 = bp0, acc1 = bp1;
            {
                const float4* wp = (const float4*)(W_proj + lane * H3);
#pragma unroll
                for (int q = 0; q < 8; q++) {
                    float4 w = wp[q];
                    acc0 += w.x * hv[q].x + w.y * hv[q].y + w.z * hv[q].z + w.w * hv[q].w;
                }
            }
            if (lane < 9) {
                const float4* wp = (const float4*)(W_proj + (32 + lane) * H3);
#pragma unroll
                for (int q = 0; q < 8; q++) {
                    float4 w = wp[q];
                    acc1 += w.x * hv[q].x + w.y * hv[q].y + w.z * hv[q].z + w.w * hv[q].w;
                }
            }
            if (b < BB) {
                float* orow = out + (size_t)(b * SS + tprev) * VOCAB;
                orow[lane] = acc0;
                if (lane < 9) orow[32 + lane] = acc1;
            }
            float bv = acc0; int bo = lane;
            if (lane < 9 && acc1 > bv) { bv = acc1; bo = 32 + lane; }
#pragma unroll
            for (int off = 16; off; off >>= 1) {
                float ov = __shfl_xor_sync(0xffffffffu, bv, off);
                int   oo = __shfl_xor_sync(0xffffffffu, bo, off);
                if (ov > bv || (ov == bv && oo < bo)) { bv = ov; bo = oo; }
            }
            if (lane == 0 && b < BB) out[PRED_OFF + b * SS + tprev] = (float)bo;
        }

        // ===== Phase A: gh0 GEMM, feat f = tid (768 feats), K=256 ==========
        if (t < SS) {
            const int f = tid;
            ull a[BROWS];
            if (f < 512) {
#pragma unroll
                for (int r = 0; r < BROWS; r++) {
                    float g = g_G0[stok[r] * G0DIM + f];
                    a[r] = packf2(g + b0, 0.0f);
                }
            } else {
#pragma unroll
                for (int r = 0; r < BROWS; r++) {
                    float g = g_G0[stok[r] * G0DIM + f];
                    sGN[r * H1 + (f - 512)] = g;
                    a[r] = packf2(b0, 0.0f);
                }
            }
            const ulonglong2* W  = (const ulonglong2*)g_Wt0 + f;
            const ulonglong2* hb = (const ulonglong2*)h0;
#pragma unroll 2
            for (int k4 = 0; k4 < 64; k4++) {
                ulonglong2 w = W[(size_t)k4 * G0DIM];
#pragma unroll
                for (int r = 0; r < BROWS; r++) {
                    ulonglong2 hv = hb[r * 64 + k4];
                    ffma2(a[r], w.x, hv.x); ffma2(a[r], w.y, hv.y);
                }
            }
#pragma unroll
            for (int r = 0; r < BROWS; r++) sGA[r * G0DIM + f] = hred(a[r]);
        }
        __syncthreads();   // S1

        // ===== combine0: new h0 =====
        if (t < SS) {
            for (int tau = tid; tau < BROWS * H1; tau += NT) {
                int r = tau >> 8, i = tau & 255;
                float pr  = sGA[r * G0DIM + i];
                float pz  = sGA[r * G0DIM + H1 + i];
                float ghn = sGA[r * G0DIM + 2 * H1 + i];
                float gin = sGN[r * H1 + i];
                float rg = sigf(pr), zg = sigf(pz);
                float ng = tanhf(fmaf(rg, ghn, gin));
                float hp = h0[r * H1 + i];
                h0[r * H1 + i] = fmaf(zg, hp - ng, ng);
            }
        }
        __syncthreads();   // S2

        // ===== Phase B: gi1 GEMM, K-split-2, 768 tasks =====
        if (t < SS) {
            const int f  = (tid < G1DIM) ? tid : tid - G1DIM;
            const int k0 = (tid < G1DIM) ? 0 : 32;
            ull a[BROWS];
            ull ini = (tid < G1DIM) ? packf2(b1i, 0.0f) : 0ull;
#pragma unroll
            for (int r = 0; r < BROWS; r++) a[r] = ini;
            const ulonglong2* W  = (const ulonglong2*)g_Wt1 + (size_t)k0 * G1DIM + f;
            const ulonglong2* hb = (const ulonglong2*)h0;
#pragma unroll 2
            for (int kk = 0; kk < 32; kk++) {
                int k4 = k0 + kk;
                ulonglong2 w = W[(size_t)kk * G1DIM];
#pragma unroll
                for (int r = 0; r < BROWS; r++) {
                    ulonglong2 hv = hb[r * 64 + k4];
                    ffma2(a[r], w.x, hv.x); ffma2(a[r], w.y, hv.y);
                }
            }
            float* dst = sGA + ((tid < G1DIM) ? 0 : BROWS * G1DIM);
#pragma unroll
            for (int r = 0; r < BROWS; r++) dst[r * G1DIM + f] = hred(a[r]);
        }
        __syncthreads();   // S3

        // ===== Phase C: gh1 GEMM, K-split-2, 768 tasks (smem+gmem weights) ==
        if (t < SS) {
            const int f  = (tid < G1DIM) ? tid : tid - G1DIM;
            const int k0 = (tid < G1DIM) ? 0 : 16;
            ull a[BROWS];
            ull ini = (tid < G1DIM) ? packf2(b1h, 0.0f) : 0ull;
#pragma unroll
            for (int r = 0; r < BROWS; r++) a[r] = ini;
            const ulonglong2* hb = (const ulonglong2*)h1;
            const ulonglong2* Ws = (const ulonglong2*)(sm + O_WHH1) + f;
            const ulonglong2* Wg = (const ulonglong2*)g_Wt1h + f;
#pragma unroll 2
            for (int kk = 0; kk < 16; kk++) {
                int k4 = k0 + kk;
                ulonglong2 w = (k4 < WSM) ? Ws[(size_t)k4 * G1DIM]
                                          : Wg[(size_t)k4 * G1DIM];
#pragma unroll
                for (int r = 0; r < BROWS; r++) {
                    ulonglong2 hv = hb[r * 32 + k4];
                    ffma2(a[r], w.x, hv.x); ffma2(a[r], w.y, hv.y);
                }
            }
            float* dst = sGB + ((tid < G1DIM) ? 0 : BROWS * G1DIM);
#pragma unroll
            for (int r = 0; r < BROWS; r++) dst[r * G1DIM + f] = hred(a[r]);
        }
        __syncthreads();   // S4

        // ===== combine1: new h1 =====
        if (t < SS) {
            for (int tau = tid; tau < BROWS * H2; tau += NT) {
                int r = tau >> 7, j = tau & 127;
                float gil = sGA[r * G1DIM + j],          gih = sGA[BROWS * G1DIM + r * G1DIM + j];
                float gzl = sGA[r * G1DIM + H2 + j],     gzh = sGA[BROWS * G1DIM + r * G1DIM + H2 + j];
                float gnl = sGA[r * G1DIM + 2*H2 + j],   gnh = sGA[BROWS * G1DIM + r * G1DIM + 2*H2 + j];
                float hrl = sGB[r * G1DIM + j],          hrh = sGB[BROWS * G1DIM + r * G1DIM + j];
                float hzl = sGB[r * G1DIM + H2 + j],     hzh = sGB[BROWS * G1DIM + r * G1DIM + H2 + j];
                float hnl = sGB[r * G1DIM + 2*H2 + j],   hnh = sGB[BROWS * G1DIM + r * G1DIM + 2*H2 + j];
                float pr  = (gil + gih) + (hrl + hrh);
                float pz  = (gzl + gzh) + (hzl + hzh);
                float gin = gnl + gnh;
                float ghn = hnl + hnh;
                float rg = sigf(pr), zg = sigf(pz);
                float ng = tanhf(fmaf(rg, ghn, gin));
                float hp = h1[r * H2 + j];
                h1[r * H2 + j] = fmaf(zg, hp - ng, ng);
            }
        }
        __syncthreads();   // S5

        // ===== Phase D: gi2 K-split-4 (384 thr) + gh2 K-split-2 (192 thr) ==
        if (t < SS && tid < 576) {
            if (tid < 384) {
                const int q = tid / G2DIM;          // 0..3
                const int f = tid - q * G2DIM;
                const int k0 = q * 8;
                ull a[BROWS];
                ull ini = (q == 0) ? packf2(b2i, 0.0f) : 0ull;
#pragma unroll
                for (int r = 0; r < BROWS; r++) a[r] = ini;
                const ulonglong2* W  = (const ulonglong2*)g_Wt2i + (size_t)k0 * G2DIM + f;
                const ulonglong2* hb = (const ulonglong2*)h1;
#pragma unroll
                for (int kk = 0; kk < 8; kk++) {
                    int k4 = k0 + kk;
                    ulonglong2 w = W[(size_t)kk * G2DIM];
#pragma unroll
                    for (int r = 0; r < BROWS; r++) {
                        ulonglong2 hv = hb[r * 32 + k4];
                        ffma2(a[r], w.x, hv.x); ffma2(a[r], w.y, hv.y);
                    }
                }
                float* dst = sGA + q * BROWS * G2DIM;
#pragma unroll
                for (int r = 0; r < BROWS; r++) dst[r * G2DIM + f] = hred(a[r]);
            } else {
                const int u = tid - 384;            // 0..191
                const int q = u / G2DIM;            // 0..1
                const int f = u - q * G2DIM;
                const int k0 = q * 4;
                ull a[BROWS];
                ull ini = (q == 0) ? packf2(b2h, 0.0f) : 0ull;
#pragma unroll
                for (int r = 0; r < BROWS; r++) a[r] = ini;
                const ulonglong2* W  = (const ulonglong2*)g_Wt2h + (size_t)k0 * G2DIM + f;
                const ulonglong2* hb = (const ulonglong2*)h2;
#pragma unroll
                for (int kk = 0; kk < 4; kk++) {
                    int k4 = k0 + kk;
                    ulonglong2 w = W[(size_t)kk * G2DIM];
#pragma unroll
                    for (int r = 0; r < BROWS; r++) {
                        ulonglong2 hv = hb[r * 8 + k4];
                        ffma2(a[r], w.x, hv.x); ffma2(a[r], w.y, hv.y);
                    }
                }
                float* dst = sGC + q * BROWS * G2DIM;
#pragma unroll
                for (int r = 0; r < BROWS; r++) dst[r * G2DIM + f] = hred(a[r]);
            }
        }
        __syncthreads();   // S6

        // ===== combine2: new h2; prefetch next tokens =====
        if (t < SS) {
            if (tid < BROWS * H3) {
                int r = tid >> 5, i = tid & 31;
                float gi_r = 0, gi_z = 0, gi_n = 0;
#pragma unroll
                for (int q = 0; q < 4; q++) {
                    const float* P = sGA + q * BROWS * G2DIM + r * G2DIM;
                    gi_r += P[i]; gi_z += P[H3 + i]; gi_n += P[2 * H3 + i];
                }
                float gh_r = 0, gh_z = 0, gh_n = 0;
#pragma unroll
                for (int q = 0; q < 2; q++) {
                    const float* P = sGC + q * BROWS * G2DIM + r * G2DIM;
                    gh_r += P[i]; gh_z += P[H3 + i]; gh_n += P[2 * H3 + i];
                }
                float rg = sigf(gi_r + gh_r), zg = sigf(gi_z + gh_z);
                float ng = tanhf(fmaf(rg, gh_n, gi_n));
                float hp = h2[r * H3 + i];
                h2[r * H3 + i] = fmaf(zg, hp - ng, ng);
            }
            if (t + 1 < SS && tid < BROWS) {
                int b = base + tid; if (b >= BB) b = BB - 1;
                stok[tid] = toks[b * SS + (t + 1)];
            }
        }
        __syncthreads();   // S7
    }
}

// ------------------------- launch (5 preps, k_gru is launch #6) -------------
extern "C" void kernel_launch(void* const* d_in, const int* in_sizes, int n_in,
                              void* d_out, int out_size) {
    const float* latent  = (const float*)d_in[0];
    const int*   ttok    = (const int*)  d_in[1];
    const float* W_emb   = (const float*)d_in[2];
    const float* b_emb   = (const float*)d_in[3];
    const float* W_init  = (const float*)d_in[4];
    const float* b_init  = (const float*)d_in[5];
    const float* Wih0    = (const float*)d_in[6];
    const float* Whh0    = (const float*)d_in[7];
    const float* bih0    = (const float*)d_in[8];
    const float* bhh0    = (const float*)d_in[9];
    const float* Wih1    = (const float*)d_in[10];
    const float* Whh1    = (const float*)d_in[11];
    const float* bih1    = (const float*)d_in[12];
    const float* bhh1    = (const float*)d_in[13];
    const float* Wih2    = (const float*)d_in[14];
    const float* Whh2    = (const float*)d_in[15];
    const float* bih2    = (const float*)d_in[16];
    const float* bhh2    = (const float*)d_in[17];
    const float* W_proj  = (const float*)d_in[18];
    const float* b_proj  = (const float*)d_in[19];
    float* out = (float*)d_out;

    k_prepA<<<(G0DIM * 64 + 255) / 256, 256>>>(Whh0, Wih1);          // 1
    k_prepB<<<(G1DIM * 32 + 255) / 256, 256>>>(Whh1, Wih2, Whh2);    // 2
    k_prepC<<<(G0DIM * LAT + 255) / 256, 256>>>(W_init, Wih0);       // 3
    k_g0   <<<VOCAB, 256>>>(W_emb, b_emb, bih0);                     // 4
    k_init <<<BB / 8, 256>>>(latent, b_init);                        // 5

    cudaFuncSetAttribute(k_gru, cudaFuncAttributeMaxDynamicSharedMemorySize, SMEM_BYTES);
    k_gru<<<NCTA, NT, SMEM_BYTES>>>(ttok, bhh0, bih1, bhh1, bih2, bhh2,
                                    W_proj, b_proj, out);            // 6  <- ncu -s 5
}